// round 7
// baseline (speedup 1.0000x reference)
#include <cuda_runtime.h>
#include <cstdint>

// Problem constants (fixed by the reference).
#define C_OUT   96
#define NK      11
#define C_IN    1056
#define GB      8
#define NTILES  (C_OUT*GB)         // 768 tiles, one per (b, c_out)
#define HOUT    56
#define WOUT    56
#define HIN     60
#define EP      2
#define PLANE   3600
#define PLANE_BYTES 14400
#define NPIX    3136
#define NCW     28                 // compute warps
#define THREADS (NCW*32 + 32)      // 928: 28 compute warps + 1 producer warp
#define OUT_PLANE ((size_t)GB*C_OUT*NPIX)
#define ROWSTEP 960                // 16*HIN

// Plane ring with shared inter-slot zero guards.
// v-row index in [-27, 86] -> offsets [-1618, +5217] from plane start;
// 1620-float guards (shared between adjacent slots) absorb all OOB reads.
#define NSLOT       10
#define NPAIR       5              // pairs (2q,2q+1) never wrap the ring
#define GUARD       1620
#define SLOT_STRIDE (PLANE + GUARD)                 // 5220
#define SM_DATA     (NSLOT*SLOT_STRIDE + GUARD)     // 53820 floats
#define OFF_TAB     SM_DATA                          // 2 x 44 float4 (double buffer)
#define OFF_WID     (OFF_TAB + 352)                  // 2 x 12 floats
#define OFF_Q       (OFF_WID + 24)                   // 4 ints (tile queue)
#define OFF_BAR     (OFF_Q + 4)                      // 5 full + 5 empty u64
#define SMEM_FLOATS (OFF_BAR + 20)
#define SMEM_BYTES  (SMEM_FLOATS * 4)                // ~216 KB

__device__ int g_tile_ctr;
__global__ void reset_kernel() { g_tile_ctr = 0; }

__device__ __forceinline__ uint32_t smem_u32(const void* p) {
    uint32_t a;
    asm("{ .reg .u64 t; cvta.to.shared.u64 t, %1; cvt.u32.u64 %0, t; }"
        : "=r"(a) : "l"(p));
    return a;
}
__device__ __forceinline__ void mbar_init(uint32_t mbar, uint32_t cnt) {
    asm volatile("mbarrier.init.shared.b64 [%0], %1;" :: "r"(mbar), "r"(cnt) : "memory");
}
__device__ __forceinline__ void mbar_wait(uint32_t mbar, int parity) {
    asm volatile(
        "{\n\t.reg .pred P;\n"
        "W_%=:\n\t"
        "mbarrier.try_wait.parity.acquire.cta.shared::cta.b64 P, [%0], %1, 0x989680;\n\t"
        "@P bra D_%=;\n\t"
        "bra W_%=;\n"
        "D_%=:\n\t}"
        :: "r"(mbar), "r"(parity) : "memory");
}

__global__ __launch_bounds__(THREADS, 1)
void addshift_kernel(const float* __restrict__ x,
                     const float* __restrict__ w1,
                     const float* __restrict__ w2,
                     const float* __restrict__ w3,
                     const int*   __restrict__ pad_hv,
                     const int*   __restrict__ idx_identit,
                     float* __restrict__ out)
{
    extern __shared__ float smem[];
    float4* tab  = (float4*)(smem + OFF_TAB);   // [2][44]
    float*  wid  = smem + OFF_WID;              // [2][12]
    int*    qarr = (int*)(smem + OFF_Q);

    const int tid = threadIdx.x;
    const uint32_t smem_base = smem_u32(smem);
    const uint32_t fbar0 = smem_base + (uint32_t)OFF_BAR * 4u;   // full[pair]
    const uint32_t ebar0 = fbar0 + 8u * NPAIR;                   // empty[pair]

    // Zero data region once (guards stay zero; plane bytes overwritten by TMA).
    {
        float4* d = (float4*)smem;
        const float4 z = make_float4(0.f, 0.f, 0.f, 0.f);
        for (int i = tid; i < SM_DATA / 4; i += THREADS) d[i] = z;
    }
    if (tid == 0) {
        for (int s = 0; s < NPAIR; s++) {
            mbar_init(fbar0 + 8u * s, 1);
            mbar_init(ebar0 + 8u * s, NCW);
        }
    }
    __syncthreads();   // the only full-CTA barrier

    // ================= producer warp =================
    if (tid >= NCW * 32) {
        if (tid == NCW * 32) {
            asm volatile("fence.proxy.async.shared::cta;" ::: "memory");
            int pnk = 0, ptq = 0;
            bool done = false;
            for (int q = 0; !done; q++) {
                int e = q % NPAIR;
                if (q >= NPAIR)
                    mbar_wait(ebar0 + 8u * e, ((q - NPAIR) / NPAIR) & 1);
                uint32_t bar = fbar0 + 8u * e;

                // plane A of the pair
                if (pnk == 0) {
                    int t = atomicAdd(&g_tile_ctr, 1);
                    qarr[ptq & 3] = (t < NTILES) ? t : -1;
                }
                int tA = qarr[ptq & 3], nkA = pnk;
                if (tA < 0) {   // sentinel as pair-first plane: plain flip, exit
                    asm volatile("mbarrier.arrive.shared.b64 _, [%0];" :: "r"(bar) : "memory");
                    break;
                }
                if (++pnk == NK) { pnk = 0; ptq++; }

                // plane B of the pair (may be a sentinel)
                if (pnk == 0) {
                    int t = atomicAdd(&g_tile_ctr, 1);
                    qarr[ptq & 3] = (t < NTILES) ? t : -1;
                }
                int tB = qarr[ptq & 3], nkB = pnk;
                bool hasB = (tB >= 0);
                if (hasB) { if (++pnk == NK) { pnk = 0; ptq++; } }
                else done = true;

                // All qarr writes above precede this release-arrive -> visible
                // to consumers at their acquire on the pair flip.
                uint32_t bytes = hasB ? 2u * PLANE_BYTES : (uint32_t)PLANE_BYTES;
                asm volatile("mbarrier.arrive.expect_tx.shared.b64 _, [%0], %1;"
                             :: "r"(bar), "r"(bytes) : "memory");

                int sA = (2 * q) % NSLOT;
                uint32_t dstA = smem_base + (uint32_t)(GUARD + sA * SLOT_STRIDE) * 4u;
                const float* srcA = x + (size_t)((tA / C_OUT) * C_IN + (tA % C_OUT) * NK + nkA) * PLANE;
                asm volatile("cp.async.bulk.shared::cta.global.mbarrier::complete_tx::bytes "
                             "[%0], [%1], %2, [%3];"
                             :: "r"(dstA), "l"(srcA), "r"((uint32_t)PLANE_BYTES), "r"(bar) : "memory");
                if (hasB) {
                    uint32_t dstB = dstA + (uint32_t)SLOT_STRIDE * 4u;
                    const float* srcB = x + (size_t)((tB / C_OUT) * C_IN + (tB % C_OUT) * NK + nkB) * PLANE;
                    asm volatile("cp.async.bulk.shared::cta.global.mbarrier::complete_tx::bytes "
                                 "[%0], [%1], %2, [%3];"
                                 :: "r"(dstB), "l"(srcB), "r"((uint32_t)PLANE_BYTES), "r"(bar) : "memory");
                }
            }
        }
        return;
    }

    // ================= compute warps =================
    const int w   = tid % WOUT;
    const int h0  = tid / WOUT;
    const int col = w + EP;
    const int rb0 = (h0 + EP) * HIN;
    const int vrow0 = h0 + EP;
    const bool k3 = (h0 < 8);
    const bool lane0 = ((tid & 31) == 0);

    int p = 0, tq = 0;
    for (;;) {
        // Wait the pair containing plane p only on even planes.
        if (!(p & 1)) {
            int q = p >> 1;
            mbar_wait(fbar0 + 8u * (q % NPAIR), (q / NPAIR) & 1);
        }
        const int t = qarr[tq & 3];
        if (t < 0) break;
        const int co = t % C_OUT, b = t / C_OUT, c0 = co * NK;

        // Double-buffered term tables for this tile.
        float4* tb = tab + (tq & 1) * 44;
        float*  wb = wid + (tq & 1) * 12;
        if (tid < 44) {
            int nk = tid >> 2, g = tid & 3, c = c0 + nk;
            float4 e;
            e.x = __int_as_float(pad_hv[c*8 + g]);
            e.y = w1[g*C_IN + c];
            e.z = __int_as_float(pad_hv[c*8 + 4 + g]);
            e.w = w2[g*C_IN + c];
            tb[tid] = e;
        }
        if (tid >= 64 && tid < 64 + NK) {
            int nk = tid - 64;
            float sw = 0.f;
            #pragma unroll
            for (int g = 0; g < 4; g++)
                if (idx_identit[co*4 + g] - c0 == nk) sw += w3[g*C_OUT + co];
            wb[nk] = sw;
        }
        asm volatile("bar.sync 1, %0;" :: "n"(NCW*32) : "memory");  // tables ready

        float acc_h[4] = {0.f,0.f,0.f,0.f};
        float acc_v[4] = {0.f,0.f,0.f,0.f};
        float acc_i[4] = {0.f,0.f,0.f,0.f};

        for (int nk = 0; nk < NK; nk++) {
            if (nk && !(p & 1)) {
                int q = p >> 1;
                mbar_wait(fbar0 + 8u * (q % NPAIR), (q / NPAIR) & 1);
            }
            const float* base = smem + GUARD + (p % NSLOT) * SLOT_STRIDE;
            const float* bh = base + rb0;
            const float* bv = base + col;

            #pragma unroll
            for (int g = 0; g < 4; g++) {
                float4 e = tb[nk*4 + g];
                int   sh = __float_as_int(e.x);
                float wh = e.y;
                int   sv = __float_as_int(e.z);
                float wv = e.w;

                int iw = col + sh;
                float wt = ((unsigned)iw < (unsigned)HIN) ? wh : 0.0f;
                const float* ph = bh + iw;                 // guards keep address safe
                acc_h[0] = fmaf(ph[0],         wt, acc_h[0]);
                acc_h[1] = fmaf(ph[ROWSTEP],   wt, acc_h[1]);
                acc_h[2] = fmaf(ph[2*ROWSTEP], wt, acc_h[2]);
                acc_h[3] = fmaf(ph[3*ROWSTEP], wt, acc_h[3]);   // k3 garbage unstored

                const float* pv = bv + (vrow0 + sv) * HIN; // OOB rows hit zero guards
                acc_v[0] = fmaf(pv[0],         wv, acc_v[0]);
                acc_v[1] = fmaf(pv[ROWSTEP],   wv, acc_v[1]);
                acc_v[2] = fmaf(pv[2*ROWSTEP], wv, acc_v[2]);
                acc_v[3] = fmaf(pv[3*ROWSTEP], wv, acc_v[3]);
            }

            float wi = wb[nk];
            if (wi != 0.0f) {      // warp-uniform branch
                const float* pi = bh + col;
                acc_i[0] = fmaf(pi[0],         wi, acc_i[0]);
                acc_i[1] = fmaf(pi[ROWSTEP],   wi, acc_i[1]);
                acc_i[2] = fmaf(pi[2*ROWSTEP], wi, acc_i[2]);
                acc_i[3] = fmaf(pi[3*ROWSTEP], wi, acc_i[3]);
            }

            // Release the PAIR once its second (odd) plane is consumed.
            // Acc register deps + in-order issue guarantee both planes' LDS
            // completed before this arrive can issue.
            if ((p & 1) && lane0) {
                int q = p >> 1;
                asm volatile("mbarrier.arrive.release.cta.shared::cta.b64 _, [%0];"
                    :: "r"(ebar0 + 8u * (q % NPAIR)),
                       "f"(acc_h[0]), "f"(acc_h[1]), "f"(acc_h[2]), "f"(acc_h[3]),
                       "f"(acc_v[0]), "f"(acc_v[1]), "f"(acc_v[2]), "f"(acc_v[3]),
                       "f"(acc_i[0]), "f"(acc_i[1]), "f"(acc_i[2]), "f"(acc_i[3])
                    : "memory");
            }
            p++;
        }

        // Write outputs (coalesced: consecutive tid -> consecutive w).
        float* oh = out;
        float* ov = out + OUT_PLANE;
        float* oi = out + 2*OUT_PLANE;
        const size_t obase = ((size_t)(b * C_OUT + co)) * NPIX + (size_t)h0 * WOUT + w;
        #pragma unroll
        for (int k = 0; k < 3; k++) {
            size_t idx = obase + (size_t)(16*k) * WOUT;
            oh[idx] = acc_h[k];
            ov[idx] = acc_v[k];
            oi[idx] = acc_i[k];
        }
        if (k3) {
            size_t idx = obase + (size_t)48 * WOUT;
            oh[idx] = acc_h[3];
            ov[idx] = acc_v[3];
            oi[idx] = acc_i[3];
        }
        tq++;
    }
}

extern "C" void kernel_launch(void* const* d_in, const int* in_sizes, int n_in,
                              void* d_out, int out_size)
{
    const float* x           = (const float*)d_in[0];
    const float* w1          = (const float*)d_in[1];
    const float* w2          = (const float*)d_in[2];
    const float* w3          = (const float*)d_in[3];
    const int*   pad_hv      = (const int*)  d_in[4];
    const int*   idx_identit = (const int*)  d_in[5];
    float*       out         = (float*)d_out;

    cudaFuncSetAttribute(addshift_kernel,
                         cudaFuncAttributeMaxDynamicSharedMemorySize, SMEM_BYTES);

    reset_kernel<<<1, 32>>>();
    addshift_kernel<<<148, THREADS, SMEM_BYTES>>>(x, w1, w2, w3, pad_hv,
                                                  idx_identit, out);
}